// round 7
// baseline (speedup 1.0000x reference)
#include <cuda_runtime.h>
#include <cstdint>
#include <cstddef>

// Problem dims (fixed by the reference)
#define Bt 1024
#define Tt 512
#define Ii 45
#define Hh 128
#define Oo 45

#define NB  7            // batch rows per CTA
#define NTH 512          // j = tid&127, quarter = tid>>7 (k/i quarter split)
#define NBLK ((Bt + NB - 1) / NB)   // 147 CTAs

#define WHH_P 130        // padded row stride for staged W_hh
#define WIH_P 50         // padded row stride for staged W_ih

// Shared-memory layout (float offsets; all even -> 8B alignment holds)
#define OFF_WHH  0                           // [j][WHH_P] raw W_hh rows
#define OFF_WIH  (Hh * WHH_P)                // [j][WIH_P] raw W_ih rows (i>=45 zero)
#define OFF_BIAS (OFF_WIH + Hh * WIH_P)      // 128
#define OFF_H    (OFF_BIAS + Hh)             // [2][7][128]  (k contiguous)
#define OFF_X    (OFF_H + 2 * 7 * Hh)        // [2][7][48]   (i contiguous)
#define OFF_PART (OFF_X + 2 * 7 * 48)        // [4][7][128] ull partials
#define SMEM_FLOATS (OFF_PART + 4 * 7 * Hh * 2)
#define SMEM_BYTES  (SMEM_FLOATS * 4)        // ~131 KB

typedef unsigned long long ull;

__device__ __forceinline__ void fma2(ull& acc, ull a, ull b) {
    asm("fma.rn.f32x2 %0, %1, %2, %0;" : "+l"(acc) : "l"(a), "l"(b));
}
__device__ __forceinline__ void add2(ull& acc, ull a) {
    asm("add.rn.f32x2 %0, %0, %1;" : "+l"(acc) : "l"(a));
}
__device__ __forceinline__ float2 unpack2(ull d) {
    unsigned lo, hi;
    asm("mov.b64 {%0, %1}, %2;" : "=r"(lo), "=r"(hi) : "l"(d));
    return make_float2(__uint_as_float(lo), __uint_as_float(hi));
}

// tanh(x) = 1 - 2/(exp(2x)+1): ~1e-6 abs err, exact +/-1 saturation.
__device__ __forceinline__ float fast_tanh(float x) {
    float e = __expf(2.0f * x);
    return 1.0f - __fdividef(2.0f, e + 1.0f);
}

__global__ void __launch_bounds__(NTH, 1)
rnn_fused_kernel(const float* __restrict__ x,
                 const float* __restrict__ W_ih,
                 const float* __restrict__ b_ih,
                 const float* __restrict__ W_hh,
                 const float* __restrict__ b_hh,
                 const float* __restrict__ W_fc,
                 const float* __restrict__ b_fc,
                 float* __restrict__ out)
{
    extern __shared__ float sm[];
    float* whh_s  = sm + OFF_WHH;   // raw rows, padded stride (staging)
    float* wih_s  = sm + OFF_WIH;
    float* bias_s = sm + OFF_BIAS;
    float* hT     = sm + OFF_H;     // [buf][row][k]
    float* xT     = sm + OFF_X;     // [buf][row][i48]
    ull*   part   = reinterpret_cast<ull*>(sm + OFF_PART);  // [q][row][j]

    const int tid = threadIdx.x;
    const int j   = tid & 127;      // hidden unit owned by this thread
    const int qt  = tid >> 7;       // quarter: k[32qt,32qt+32), i[12qt,12qt+12)
    const int rowBase = blockIdx.x * NB;

    // ---- Stage raw weights (coalesced gmem read), bias, zero h/x ----
    for (int idx = tid; idx < Hh * Hh; idx += NTH) {
        int jj = idx >> 7, kk = idx & 127;
        whh_s[jj * WHH_P + kk] = W_hh[idx];
    }
    for (int idx = tid; idx < Hh * 48; idx += NTH) {
        int jj = idx / 48, ii = idx - jj * 48;
        wih_s[jj * WIH_P + ii] = (ii < Ii) ? W_ih[jj * Ii + ii] : 0.0f;
    }
    if (tid < Hh) bias_s[tid] = b_ih[tid] + b_hh[tid];
    for (int idx = tid; idx < 2 * 7 * Hh; idx += NTH) hT[idx] = 0.0f;
    for (int idx = tid; idx < 2 * 7 * 48; idx += NTH) xT[idx] = 0.0f;
    __syncthreads();

    // ---- Pull this thread's weight slice into registers, packed over k ----
    ull wk2[16], wi2[6];
    {
        const float* wr = whh_s + j * WHH_P + qt * 32;
        #pragma unroll
        for (int q = 0; q < 16; ++q)
            wk2[q] = *reinterpret_cast<const ull*>(wr + 2 * q);
        const float* wir = wih_s + j * WIH_P + qt * 12;
        #pragma unroll
        for (int q = 0; q < 6; ++q)
            wi2[q] = *reinterpret_cast<const ull*>(wir + 2 * q);
    }
    const float bi = bias_s[j];

    // ---- x stager: 512 threads cover NB*Ii = 315 elems (<=1 each) ----
    const bool a0 = tid < NB * Ii;
    const int b0 = a0 ? tid / Ii : 0;
    const int i0 = tid - b0 * Ii;
    const bool val0 = a0 && (rowBase + b0 < Bt);
    const float* g0 = x + ((size_t)(rowBase + b0) * Tt) * Ii + i0;
    const int s0 = b0 * 48 + i0;                 // [row][i] layout

    // Stage x for t = 0 into buffer 0
    if (a0) xT[s0] = val0 ? g0[0] : 0.0f;
    __syncthreads();

    for (int t = 0; t < Tt; ++t) {
        const int cur = t & 1;
        const float* hc = hT + cur * (7 * Hh) + qt * 32;   // this quarter's k slice
        const float* xc = xT + cur * (7 * 48) + qt * 12;   // this quarter's i slice

        // Prefetch next-step x (hidden behind the FMA loops)
        float n0 = 0.0f;
        if (t + 1 < Tt && val0) n0 = g0[(t + 1) * Ii];

        // Packed accumulators per batch row: lanes = (even-k sum, odd-k sum)
        ull acc[7];
        #pragma unroll
        for (int r = 0; r < 7; ++r) acc[r] = 0ull;

        // Input contribution: 3 i-quads, broadcast LDS.128 per (row, quad)
        #pragma unroll
        for (int q = 0; q < 3; ++q) {
            const ull w0 = wi2[2 * q], w1 = wi2[2 * q + 1];
            #pragma unroll
            for (int r = 0; r < 7; ++r) {
                const ulonglong2 v =
                    *reinterpret_cast<const ulonglong2*>(xc + r * 48 + q * 4);
                fma2(acc[r], w0, v.x);
                fma2(acc[r], w1, v.y);
            }
        }

        // Recurrent contribution: 8 k-quads
        #pragma unroll
        for (int q = 0; q < 8; ++q) {
            const ull w0 = wk2[2 * q], w1 = wk2[2 * q + 1];
            #pragma unroll
            for (int r = 0; r < 7; ++r) {
                const ulonglong2 v =
                    *reinterpret_cast<const ulonglong2*>(hc + r * Hh + q * 4);
                fma2(acc[r], w0, v.x);
                fma2(acc[r], w1, v.y);
            }
        }

        // Post partials for rows this quarter does NOT finish (finisher(r) = r>>1)
        ull* myp = part + (qt * 7) * Hh + j;
        #pragma unroll
        for (int r = 0; r < 7; ++r)
            if ((r >> 1) != qt) myp[r * Hh] = acc[r];
        __syncthreads();

        // Finish rows {2qt, 2qt+1} (quarter 3 finishes only row 6)
        float* hn = hT + (cur ^ 1) * (7 * Hh);
        #pragma unroll
        for (int rr = 0; rr < 2; ++rr) {
            const int r = 2 * qt + rr;
            if (r < 7) {
                ull a = acc[r];
                #pragma unroll
                for (int qq = 0; qq < 4; ++qq)
                    if (qq != qt) add2(a, part[(qq * 7 + r) * Hh + j]);
                const float2 f = unpack2(a);
                hn[r * Hh + j] = fast_tanh(f.x + f.y + bi);
            }
        }

        // Store prefetched x into the other buffer (pads stay 0)
        if (a0) xT[(cur ^ 1) * (7 * 48) + s0] = n0;

        __syncthreads();
    }

    // ---- Final FC: out[b][o] = b_fc[o] + sum_j W_fc[o][j] * h_last[b][j] ----
    // Tt even -> last h landed in buffer 0. Layout [row][j], contiguous in j.
    const float* hlast = hT;
    if (tid < NB * Oo) {
        const int b = tid / Oo;
        const int o = tid - b * Oo;
        const int row = rowBase + b;
        if (row < Bt) {
            float s = b_fc[o];
            const float* wp = W_fc + o * Hh;
            const float* hp = hlast + b * Hh;
            #pragma unroll 8
            for (int jj = 0; jj < Hh; ++jj)
                s = fmaf(wp[jj], hp[jj], s);
            out[row * Oo + o] = s;
        }
    }
}

extern "C" void kernel_launch(void* const* d_in, const int* in_sizes, int n_in,
                              void* d_out, int out_size)
{
    const float* x   = (const float*)d_in[0];
    const float* Wih = (const float*)d_in[1];
    const float* bih = (const float*)d_in[2];
    const float* Whh = (const float*)d_in[3];
    const float* bhh = (const float*)d_in[4];
    const float* Wfc = (const float*)d_in[5];
    const float* bfc = (const float*)d_in[6];
    float* out = (float*)d_out;

    cudaFuncSetAttribute(rnn_fused_kernel,
                         cudaFuncAttributeMaxDynamicSharedMemorySize, SMEM_BYTES);
    rnn_fused_kernel<<<NBLK, NTH, SMEM_BYTES>>>(x, Wih, bih, Whh, bhh, Wfc, bfc, out);
}

// round 8
// speedup vs baseline: 1.0353x; 1.0353x over previous
#include <cuda_runtime.h>
#include <cstdint>
#include <cstddef>

// Problem dims (fixed by the reference)
#define Bt 1024
#define Tt 512
#define Ii 45
#define Hh 128
#define Oo 45

#define NB  7            // batch rows per CTA
#define NTH 256          // jp = tid&63 -> j{2jp,2jp+1}; qt = tid>>6 -> k/i quarter
#define NBLK ((Bt + NB - 1) / NB)   // 147 CTAs

#define WHH_P 130        // padded row stride for staged W_hh
#define WIH_P 50         // padded row stride for staged W_ih

// Shared-memory layout (float offsets; OFF_PART is 16B-aligned)
#define OFF_WHH  0                           // [j][WHH_P] raw W_hh rows
#define OFF_WIH  (Hh * WHH_P)                // [j][WIH_P] raw W_ih rows (i>=45 zero)
#define OFF_BIAS (OFF_WIH + Hh * WIH_P)      // 128
#define OFF_H    (OFF_BIAS + Hh)             // [2][7][128]  (k contiguous)
#define OFF_X    (OFF_H + 2 * 7 * Hh)        // [2][7][48]   (i contiguous)
#define OFF_PART (OFF_X + 2 * 7 * 48)        // [4][7][128] ull partials
#define SMEM_FLOATS (OFF_PART + 4 * 7 * Hh * 2)
#define SMEM_BYTES  (SMEM_FLOATS * 4)        // ~131 KB

typedef unsigned long long ull;

__device__ __forceinline__ void fma2(ull& acc, ull a, ull b) {
    asm("fma.rn.f32x2 %0, %1, %2, %0;" : "+l"(acc) : "l"(a), "l"(b));
}
__device__ __forceinline__ void add2(ull& acc, ull a) {
    asm("add.rn.f32x2 %0, %0, %1;" : "+l"(acc) : "l"(a));
}
__device__ __forceinline__ float2 unpack2(ull d) {
    unsigned lo, hi;
    asm("mov.b64 {%0, %1}, %2;" : "=r"(lo), "=r"(hi) : "l"(d));
    return make_float2(__uint_as_float(lo), __uint_as_float(hi));
}

// tanh(x) = 1 - 2/(exp(2x)+1): ~1e-6 abs err, exact +/-1 saturation.
__device__ __forceinline__ float fast_tanh(float x) {
    float e = __expf(2.0f * x);
    return 1.0f - __fdividef(2.0f, e + 1.0f);
}

__global__ void __launch_bounds__(NTH, 1)
rnn_fused_kernel(const float* __restrict__ x,
                 const float* __restrict__ W_ih,
                 const float* __restrict__ b_ih,
                 const float* __restrict__ W_hh,
                 const float* __restrict__ b_hh,
                 const float* __restrict__ W_fc,
                 const float* __restrict__ b_fc,
                 float* __restrict__ out)
{
    extern __shared__ float sm[];
    float* whh_s  = sm + OFF_WHH;   // raw rows, padded stride (staging)
    float* wih_s  = sm + OFF_WIH;
    float* bias_s = sm + OFF_BIAS;
    float* hT     = sm + OFF_H;     // [buf][row][k]
    float* xT     = sm + OFF_X;     // [buf][row][i48]
    ull*   part   = reinterpret_cast<ull*>(sm + OFF_PART);  // [q][row][j]

    const int tid = threadIdx.x;
    const int jp  = tid & 63;       // j pair owned: j0 = 2jp, j1 = 2jp+1
    const int qt  = tid >> 6;       // quarter: k[32qt,32qt+32), i[12qt,12qt+12)
    const int j0  = 2 * jp, j1 = 2 * jp + 1;
    const int rowBase = blockIdx.x * NB;

    // ---- Stage raw weights (coalesced gmem read), bias, zero h/x ----
    for (int idx = tid; idx < Hh * Hh; idx += NTH) {
        int jj = idx >> 7, kk = idx & 127;
        whh_s[jj * WHH_P + kk] = W_hh[idx];
    }
    for (int idx = tid; idx < Hh * 48; idx += NTH) {
        int jj = idx / 48, ii = idx - jj * 48;
        wih_s[jj * WIH_P + ii] = (ii < Ii) ? W_ih[jj * Ii + ii] : 0.0f;
    }
    if (tid < Hh) bias_s[tid] = b_ih[tid] + b_hh[tid];
    for (int idx = tid; idx < 2 * 7 * Hh; idx += NTH) hT[idx] = 0.0f;
    for (int idx = tid; idx < 2 * 7 * 48; idx += NTH) xT[idx] = 0.0f;
    __syncthreads();

    // ---- Pull BOTH j columns' weight slices into registers, packed over k ----
    ull wkA[16], wkB[16], wiA[6], wiB[6];
    {
        const float* wa = whh_s + j0 * WHH_P + qt * 32;
        const float* wb = whh_s + j1 * WHH_P + qt * 32;
        #pragma unroll
        for (int q = 0; q < 16; ++q) {
            wkA[q] = *reinterpret_cast<const ull*>(wa + 2 * q);
            wkB[q] = *reinterpret_cast<const ull*>(wb + 2 * q);
        }
        const float* ia = wih_s + j0 * WIH_P + qt * 12;
        const float* ib = wih_s + j1 * WIH_P + qt * 12;
        #pragma unroll
        for (int q = 0; q < 6; ++q) {
            wiA[q] = *reinterpret_cast<const ull*>(ia + 2 * q);
            wiB[q] = *reinterpret_cast<const ull*>(ib + 2 * q);
        }
    }
    const float bi0 = bias_s[j0];
    const float bi1 = bias_s[j1];

    // ---- x stager: 256 threads cover NB*Ii = 315 elems (<=2 each) ----
    const int e0 = tid, e1 = tid + NTH;
    const bool a1 = e1 < NB * Ii;                 // e0 < 315 always
    const int b0 = e0 / Ii, b1 = a1 ? e1 / Ii : 0;
    const int i0 = e0 - b0 * Ii, i1 = e1 - b1 * Ii;
    const bool val0 = (rowBase + b0 < Bt);
    const bool val1 = a1 && (rowBase + b1 < Bt);
    const float* g0 = x + ((size_t)(rowBase + b0) * Tt) * Ii + i0;
    const float* g1 = x + ((size_t)(rowBase + b1) * Tt) * Ii + i1;
    const int s0 = b0 * 48 + i0, s1 = b1 * 48 + i1;   // [row][i] layout

    // Stage x for t = 0 into buffer 0
    xT[s0] = val0 ? g0[0] : 0.0f;
    if (a1) xT[s1] = val1 ? g1[0] : 0.0f;
    __syncthreads();

    for (int t = 0; t < Tt; ++t) {
        const int cur = t & 1;
        const float* hc = hT + cur * (7 * Hh) + qt * 32;   // this quarter's k slice
        const float* xc = xT + cur * (7 * 48) + qt * 12;   // this quarter's i slice

        // Prefetch next-step x (hidden behind the FMA loops)
        float n0 = 0.0f, n1 = 0.0f;
        if (t + 1 < Tt) {
            const int off = (t + 1) * Ii;
            if (val0) n0 = g0[off];
            if (val1) n1 = g1[off];
        }

        // Packed accumulators per (j, row): lanes = (even-k, odd-k) partial sums
        ull aA[7], aB[7];
        #pragma unroll
        for (int r = 0; r < 7; ++r) { aA[r] = 0ull; aB[r] = 0ull; }

        // Input contribution: 3 i-quads; each LDS.128 feeds 4 fma2
        #pragma unroll
        for (int q = 0; q < 3; ++q) {
            const ull wA0 = wiA[2 * q], wA1 = wiA[2 * q + 1];
            const ull wB0 = wiB[2 * q], wB1 = wiB[2 * q + 1];
            #pragma unroll
            for (int r = 0; r < 7; ++r) {
                const ulonglong2 v =
                    *reinterpret_cast<const ulonglong2*>(xc + r * 48 + q * 4);
                fma2(aA[r], wA0, v.x); fma2(aA[r], wA1, v.y);
                fma2(aB[r], wB0, v.x); fma2(aB[r], wB1, v.y);
            }
        }

        // Recurrent contribution: 8 k-quads; each LDS.128 feeds 4 fma2
        #pragma unroll
        for (int q = 0; q < 8; ++q) {
            const ull wA0 = wkA[2 * q], wA1 = wkA[2 * q + 1];
            const ull wB0 = wkB[2 * q], wB1 = wkB[2 * q + 1];
            #pragma unroll
            for (int r = 0; r < 7; ++r) {
                const ulonglong2 v =
                    *reinterpret_cast<const ulonglong2*>(hc + r * Hh + q * 4);
                fma2(aA[r], wA0, v.x); fma2(aA[r], wA1, v.y);
                fma2(aB[r], wB0, v.x); fma2(aB[r], wB1, v.y);
            }
        }

        // Post partials (both j, 16B STS) for rows this quarter does NOT finish
        ull* myp = part + (qt * 7) * Hh + j0;
        #pragma unroll
        for (int r = 0; r < 7; ++r) {
            if ((r >> 1) != qt) {
                ulonglong2 v; v.x = aA[r]; v.y = aB[r];
                *reinterpret_cast<ulonglong2*>(myp + r * Hh) = v;
            }
        }
        __syncthreads();

        // Finish rows {2qt, 2qt+1} (quarter 3 finishes only row 6)
        float* hn = hT + (cur ^ 1) * (7 * Hh);
        #pragma unroll
        for (int rr = 0; rr < 2; ++rr) {
            const int r = 2 * qt + rr;
            if (r < 7) {
                ull s0a = aA[r], s1a = aB[r];
                #pragma unroll
                for (int qq = 0; qq < 4; ++qq) {
                    if (qq != qt) {
                        const ulonglong2 p = *reinterpret_cast<const ulonglong2*>(
                            part + (qq * 7 + r) * Hh + j0);
                        add2(s0a, p.x);
                        add2(s1a, p.y);
                    }
                }
                const float2 f0 = unpack2(s0a);
                const float2 f1 = unpack2(s1a);
                float2 o;
                o.x = fast_tanh(f0.x + f0.y + bi0);
                o.y = fast_tanh(f1.x + f1.y + bi1);
                *reinterpret_cast<float2*>(hn + r * Hh + j0) = o;
            }
        }

        // Store prefetched x into the other buffer (pads stay 0)
        float* xn = xT + (cur ^ 1) * (7 * 48);
        xn[s0] = n0;
        if (a1) xn[s1] = n1;

        __syncthreads();
    }

    // ---- Final FC: out[b][o] = b_fc[o] + sum_j W_fc[o][j] * h_last[b][j] ----
    // Tt even -> last h landed in buffer 0. Layout [row][j], contiguous in j.
    const float* hlast = hT;
    for (int idx = tid; idx < NB * Oo; idx += NTH) {
        const int b = idx / Oo;
        const int o = idx - b * Oo;
        const int row = rowBase + b;
        if (row < Bt) {
            float s = b_fc[o];
            const float* wp = W_fc + o * Hh;
            const float* hp = hlast + b * Hh;
            #pragma unroll 8
            for (int jj = 0; jj < Hh; ++jj)
                s = fmaf(wp[jj], hp[jj], s);
            out[row * Oo + o] = s;
        }
    }
}

extern "C" void kernel_launch(void* const* d_in, const int* in_sizes, int n_in,
                              void* d_out, int out_size)
{
    const float* x   = (const float*)d_in[0];
    const float* Wih = (const float*)d_in[1];
    const float* bih = (const float*)d_in[2];
    const float* Whh = (const float*)d_in[3];
    const float* bhh = (const float*)d_in[4];
    const float* Wfc = (const float*)d_in[5];
    const float* bfc = (const float*)d_in[6];
    float* out = (float*)d_out;

    cudaFuncSetAttribute(rnn_fused_kernel,
                         cudaFuncAttributeMaxDynamicSharedMemorySize, SMEM_BYTES);
    rnn_fused_kernel<<<NBLK, NTH, SMEM_BYTES>>>(x, Wih, bih, Whh, bhh, Wfc, bfc, out);
}

// round 9
// speedup vs baseline: 1.0671x; 1.0307x over previous
#include <cuda_runtime.h>
#include <cstdint>
#include <cstddef>

// Problem dims (fixed by the reference)
#define Bt 1024
#define Tt 512
#define Ii 45
#define Hh 128
#define Oo 45

#define NBMAX 4          // max batch rows per CTA (balanced 3-4)
#define NTH 256          // jp = tid&63 -> j{2jp,2jp+1}; qt = tid>>6 -> k/i quarter
#define NBLK 294         // 2 CTAs per SM, single wave

// Shared-memory layout (float offsets)
#define OFF_H    0                       // [2][4][128] h double buffer, [row][k]
#define OFF_X    (2 * NBMAX * Hh)        // [2][4][48]  x double buffer, [row][i]
#define OFF_PART (OFF_X + 2 * NBMAX * 48)// [4][4][128] ull partials (16B aligned)
#define SMEM_FLOATS (OFF_PART + 4 * NBMAX * Hh * 2)
#define SMEM_BYTES  (SMEM_FLOATS * 4)    // ~22 KB -> 2 CTAs/SM

typedef unsigned long long ull;

__device__ __forceinline__ void fma2(ull& acc, ull a, ull b) {
    asm("fma.rn.f32x2 %0, %1, %2, %0;" : "+l"(acc) : "l"(a), "l"(b));
}
__device__ __forceinline__ void add2(ull& acc, ull a) {
    asm("add.rn.f32x2 %0, %0, %1;" : "+l"(acc) : "l"(a));
}
__device__ __forceinline__ float2 unpack2(ull d) {
    unsigned lo, hi;
    asm("mov.b64 {%0, %1}, %2;" : "=r"(lo), "=r"(hi) : "l"(d));
    return make_float2(__uint_as_float(lo), __uint_as_float(hi));
}
__device__ __forceinline__ ull pack2f(float lo, float hi) {
    ull d;
    asm("mov.b64 %0, {%1, %2};" : "=l"(d)
        : "r"(__float_as_uint(lo)), "r"(__float_as_uint(hi)));
    return d;
}

// tanh(x) = 1 - 2/(exp(2x)+1): ~1e-6 abs err, exact +/-1 saturation.
__device__ __forceinline__ float fast_tanh(float x) {
    float e = __expf(2.0f * x);
    return 1.0f - __fdividef(2.0f, e + 1.0f);
}

__global__ void __launch_bounds__(NTH, 2)
rnn_fused_kernel(const float* __restrict__ x,
                 const float* __restrict__ W_ih,
                 const float* __restrict__ b_ih,
                 const float* __restrict__ W_hh,
                 const float* __restrict__ b_hh,
                 const float* __restrict__ W_fc,
                 const float* __restrict__ b_fc,
                 float* __restrict__ out)
{
    extern __shared__ float sm[];
    float* hT   = sm + OFF_H;     // [buf][row][k]
    float* xT   = sm + OFF_X;     // [buf][row][i48]
    ull*   part = reinterpret_cast<ull*>(sm + OFF_PART);  // [q][row][j]

    const int tid = threadIdx.x;
    const int jp  = tid & 63;       // j pair: j0 = 2jp, j1 = 2jp+1
    const int qt  = tid >> 6;       // quarter: k[32qt,32qt+32), i[12qt,12qt+12)
    const int j0  = 2 * jp, j1 = 2 * jp + 1;

    // Balanced row split: rows [rowStart, rowEnd), nb in {3,4}
    const int bid = blockIdx.x;
    const int rowStart = (bid * Bt) / NBLK;
    const int rowEnd   = ((bid + 1) * Bt) / NBLK;
    const int nb = rowEnd - rowStart;

    // ---- Zero h and x double buffers (pad rows stay zero forever) ----
    for (int idx = tid; idx < 2 * NBMAX * Hh; idx += NTH) hT[idx] = 0.0f;
    for (int idx = tid; idx < 2 * NBMAX * 48; idx += NTH) xT[idx] = 0.0f;

    // ---- Load this thread's weights straight from GMEM into registers ----
    // W_hh rows j0/j1, k slice [32qt, 32qt+32): 8B-aligned ull loads
    ull wkA[16], wkB[16];
    {
        const float* wa = W_hh + j0 * Hh + qt * 32;
        const float* wb = W_hh + j1 * Hh + qt * 32;
        #pragma unroll
        for (int q = 0; q < 16; ++q) {
            wkA[q] = *reinterpret_cast<const ull*>(wa + 2 * q);
            wkB[q] = *reinterpret_cast<const ull*>(wb + 2 * q);
        }
    }
    // W_ih rows j0/j1, i slice [12qt, 12qt+12) (i>=45 -> 0), scalar then pack
    ull wiA[6], wiB[6];
    {
        #pragma unroll
        for (int q = 0; q < 6; ++q) {
            const int ia = qt * 12 + 2 * q, ib = ia + 1;
            const float a0 = (ia < Ii) ? W_ih[j0 * Ii + ia] : 0.0f;
            const float a1 = (ib < Ii) ? W_ih[j0 * Ii + ib] : 0.0f;
            const float c0 = (ia < Ii) ? W_ih[j1 * Ii + ia] : 0.0f;
            const float c1 = (ib < Ii) ? W_ih[j1 * Ii + ib] : 0.0f;
            wiA[q] = pack2f(a0, a1);
            wiB[q] = pack2f(c0, c1);
        }
    }
    const float bi0 = b_ih[j0] + b_hh[j0];
    const float bi1 = b_ih[j1] + b_hh[j1];

    // ---- x stager: one element per thread (nb*Ii <= 180 < 256) ----
    const bool a0 = tid < nb * Ii;
    const int br = a0 ? tid / Ii : 0;
    const int ir = tid - br * Ii;
    const float* g0 = x + ((size_t)(rowStart + br) * Tt) * Ii + ir;
    const int s0 = br * 48 + ir;                 // [row][i48] layout

    __syncthreads();   // zero-fill visible

    if (a0) xT[s0] = g0[0];
    __syncthreads();

    for (int t = 0; t < Tt; ++t) {
        const int cur = t & 1;
        const float* hc = hT + cur * (NBMAX * Hh) + qt * 32;
        const float* xc = xT + cur * (NBMAX * 48) + qt * 12;

        // Prefetch next-step x (hidden behind the FMA loops)
        float n0 = 0.0f;
        if (t + 1 < Tt && a0) n0 = g0[(t + 1) * Ii];

        // Packed accumulators per (j, row): lanes = (even-k, odd-k) partials
        ull aA[NBMAX], aB[NBMAX];
        #pragma unroll
        for (int r = 0; r < NBMAX; ++r) { aA[r] = 0ull; aB[r] = 0ull; }

        // Input contribution: 3 i-quads; each broadcast LDS.128 feeds 4 fma2
        #pragma unroll
        for (int q = 0; q < 3; ++q) {
            const ull wA0 = wiA[2 * q], wA1 = wiA[2 * q + 1];
            const ull wB0 = wiB[2 * q], wB1 = wiB[2 * q + 1];
            #pragma unroll
            for (int r = 0; r < NBMAX; ++r) {
                const ulonglong2 v =
                    *reinterpret_cast<const ulonglong2*>(xc + r * 48 + q * 4);
                fma2(aA[r], wA0, v.x); fma2(aA[r], wA1, v.y);
                fma2(aB[r], wB0, v.x); fma2(aB[r], wB1, v.y);
            }
        }

        // Recurrent contribution: 8 k-quads
        #pragma unroll
        for (int q = 0; q < 8; ++q) {
            const ull wA0 = wkA[2 * q], wA1 = wkA[2 * q + 1];
            const ull wB0 = wkB[2 * q], wB1 = wkB[2 * q + 1];
            #pragma unroll
            for (int r = 0; r < NBMAX; ++r) {
                const ulonglong2 v =
                    *reinterpret_cast<const ulonglong2*>(hc + r * Hh + q * 4);
                fma2(aA[r], wA0, v.x); fma2(aA[r], wA1, v.y);
                fma2(aB[r], wB0, v.x); fma2(aB[r], wB1, v.y);
            }
        }

        // Post partials (16B STS) for the 3 rows this quarter does not finish
        ull* myp = part + (qt * NBMAX) * Hh + j0;
        #pragma unroll
        for (int r = 0; r < NBMAX; ++r) {
            if (r != qt) {
                ulonglong2 v; v.x = aA[r]; v.y = aB[r];
                *reinterpret_cast<ulonglong2*>(myp + r * Hh) = v;
            }
        }
        __syncthreads();

        // Finish row r == qt (each thread finishes exactly one row, both j)
        {
            const int r = qt;
            ull sA = aA[r], sB = aB[r];
            #pragma unroll
            for (int qq = 0; qq < 4; ++qq) {
                if (qq != qt) {
                    const ulonglong2 p = *reinterpret_cast<const ulonglong2*>(
                        part + (qq * NBMAX + r) * Hh + j0);
                    add2(sA, p.x);
                    add2(sB, p.y);
                }
            }
            const float2 fA = unpack2(sA);
            const float2 fB = unpack2(sB);
            float2 o;
            o.x = fast_tanh(fA.x + fA.y + bi0);
            o.y = fast_tanh(fB.x + fB.y + bi1);
            float* hn = hT + (cur ^ 1) * (NBMAX * Hh);
            *reinterpret_cast<float2*>(hn + r * Hh + j0) = o;
        }

        // Store prefetched x into the other buffer (pad rows stay 0)
        if (a0) xT[(cur ^ 1) * (NBMAX * 48) + s0] = n0;

        __syncthreads();
    }

    // ---- Final FC: out[b][o] = b_fc[o] + sum_j W_fc[o][j] * h_last[b][j] ----
    // Tt even -> last h landed in buffer 0. Layout [row][j], contiguous in j.
    const float* hlast = hT;
    if (tid < nb * Oo) {
        const int b = tid / Oo;
        const int o = tid - b * Oo;
        float s = b_fc[o];
        const float* wp = W_fc + o * Hh;
        const float* hp = hlast + b * Hh;
        #pragma unroll 8
        for (int jj = 0; jj < Hh; ++jj)
            s = fmaf(wp[jj], hp[jj], s);
        out[(rowStart + b) * Oo + o] = s;
    }
}

extern "C" void kernel_launch(void* const* d_in, const int* in_sizes, int n_in,
                              void* d_out, int out_size)
{
    const float* x   = (const float*)d_in[0];
    const float* Wih = (const float*)d_in[1];
    const float* bih = (const float*)d_in[2];
    const float* Whh = (const float*)d_in[3];
    const float* bhh = (const float*)d_in[4];
    const float* Wfc = (const float*)d_in[5];
    const float* bfc = (const float*)d_in[6];
    float* out = (float*)d_out;

    rnn_fused_kernel<<<NBLK, NTH, SMEM_BYTES>>>(x, Wih, bih, Whh, bhh, Wfc, bfc, out);
}